// round 10
// baseline (speedup 1.0000x reference)
#include <cuda_runtime.h>
#include <cuda_fp16.h>
#include <math.h>
#include <stdint.h>

#define NODECAP 16384
#define G_TOTAL 237568   // 192*384 + 256*512 + 128*256
#define PRECAP  (1<<20)
#define SMEM_BYTES 65536    // 2 mats * 64 edges * 256 cols * 2B

// Prepped fragment-major fp16 weights: [0]=q [1]=k
__device__ __align__(16) __half g_B[2][G_TOTAL];
__device__ float    g_pre[PRECAP];
__device__ unsigned g_segmax[NODECAP * 8];
__device__ float    g_segsum[NODECAP * 8];

__constant__ int c_ord[9] = {0, 2, 6, 3, 7, 1, 5, 8, 4};
__constant__ int c_KT[3]  = {12, 16, 8};
__constant__ int c_NP[3]  = {24, 32, 16};
__constant__ int c_NPJ[3] = {3, 4, 2};          // NP / 8
__constant__ int c_D[3]   = {192, 256, 128};
__constant__ int c_IB0[3] = {0, 3, 7};
__constant__ int c_B4[3]  = {0, 9216, 25600};   // uint4 base per group

// ---------------------------------------------------------------------------
// Weight prep: dense W_eff per |m| group (sign pattern folded), fp16,
// exact mma.m16n8k16 B-fragment order, n8 pairs packed 8 halfs/lane.
// ---------------------------------------------------------------------------
__global__ void prep_w(const float* __restrict__ W, int mat) {
    int idx = blockIdx.x * blockDim.x + threadIdx.x;
    if (idx >= G_TOTAL) return;
    int g, kk, n, NP, boff, rem = idx;
    if (rem < 73728)       { g = 0; kk = rem / 384; n = rem % 384; NP = 24; boff = 0; }
    else if (rem < 204800) { rem -= 73728;  g = 1; kk = rem / 512; n = rem % 512; NP = 32; boff = 73728; }
    else                   { rem -= 204800; g = 2; kk = rem / 256; n = rem % 256; NP = 16; boff = 204800; }

    int c = kk & 63, d = n & 127, ib = kk >> 6, ob = n >> 7;
    int w; float s = 1.0f;
    if (g == 0) {
        w = ib * 3 + ob;
    } else if (g == 1) {
        int i = ib & 1, o = ob & 1;
        bool ip = ib < 2, op = ob < 2;
        int base = 9 + i * 4 + o * 2;
        if (ip && op)        w = base;                   // +Wr
        else if (!ip && op)  { w = base + 1; s = -1.f; } // -Wi
        else if (ip && !op)  w = base + 1;               // +Wi
        else                 w = base;                   // +Wr
    } else {
        bool ip = (ib == 0), op = (ob == 0);
        if (ip && op)        w = 17;
        else if (!ip && op)  { w = 18; s = -1.f; }
        else if (ip && !op)  w = 18;
        else                 w = 17;
    }
    int widx = (w * 64 + c) * 128 + d;

    int kt = kk >> 4, k16 = kk & 15, n8 = n >> 3;
    int lane = (n & 7) * 4 + ((k16 & 7) >> 1);
    int slot = (k16 & 1) + ((k16 >> 3) << 1);
    int off  = boff + ((kt * NP + (n8 >> 1)) * 32 + lane) * 8 + ((n8 & 1) << 2) + slot;

    g_B[mat][off] = __float2half(s * W[widx]);
}

// ---------------------------------------------------------------------------
#define MMA(c, a, b0, b1) asm volatile( \
    "mma.sync.aligned.m16n8k16.row.col.f32.f16.f16.f32 " \
    "{%0,%1,%2,%3},{%4,%5,%6,%7},{%8,%9},{%0,%1,%2,%3};\n" \
    : "+f"((c)[0]), "+f"((c)[1]), "+f"((c)[2]), "+f"((c)[3]) \
    : "r"((a).x), "r"((a).y), "r"((a).z), "r"((a).w), "r"(b0), "r"(b1))

#define PF_L1(p) asm volatile("prefetch.global.L1 [%0];" :: "l"(p))

__global__ __launch_bounds__(256, 2)
void so2_attn_main(const float* __restrict__ xq, const float* __restrict__ xk, int E) {
    extern __shared__ __half sA[];   // [0]=q frags (16384 halfs), [16384]=k frags
    const int tid = threadIdx.x, lane = tid & 31, warp = tid >> 5;
    const int warpM = warp & 1, warpN = warp >> 1;
    const int tileE = blockIdx.x * 64;

    float pre[2][2][2];   // [mt][rowhalf][np] ; head = warpN + np*4
    #pragma unroll
    for (int a = 0; a < 2; a++)
        #pragma unroll
        for (int b = 0; b < 2; b++)
            #pragma unroll
            for (int c = 0; c < 2; c++) pre[a][b][c] = 0.f;

    for (int g = 0; g < 3; ++g) {
        const int Kt = c_KT[g], NP = c_NP[g], NPJ = c_NPJ[g], D = c_D[g];
        __syncthreads();   // previous group's compute fully done before rewriting sA
        // ---- convert x slice -> fragment-major fp16 smem (64 edges) ----
        const int nq = 64 * (D >> 2);
        #pragma unroll
        for (int t = 0; t < 2; ++t) {
            const float* x = t ? xk : xq;
            __half* A = sA + t * 16384;
            for (int q0 = tid; q0 < nq; q0 += 256) {
                int el = q0 / (D >> 2), c = (q0 % (D >> 2)) * 4;
                int ord = c_ord[c_IB0[g] + (c >> 6)];
                int e = tileE + el;
                float4 v = make_float4(0.f, 0.f, 0.f, 0.f);
                if (e < E) v = *(const float4*)(x + ((size_t)e * 9 + ord) * 64 + (c & 63));
                int r = el & 15, mtile = el >> 4;
                int kt = c >> 4, kk0 = c & 15;
                int ln0 = (r & 7) * 4 + ((kk0 & 7) >> 1);
                int hx  = (((kk0 >> 3) << 1) + (r >> 3)) * 2;
                int off = ((mtile * Kt + kt) * 32 + ln0) * 8 + hx;
                *(__half2*)(A + off)     = __floats2half2_rn(v.x, v.y);
                *(__half2*)(A + off + 8) = __floats2half2_rn(v.z, v.w);
            }
        }
        __syncthreads();

        // ---- fused fp16 GEMMs + per-head q*k reduction ----
        // B read directly from L2/L1 with a software prefetch cursor 2 steps
        // ahead (prefetch.global.L1), so the in-loop LDGs are L1 hits.
        const uint4* Bq = (const uint4*)g_B[0] + c_B4[g];
        const uint4* Bk = (const uint4*)g_B[1] + c_B4[g];
        const uint4* Aq = (const uint4*)sA;
        const uint4* Ak = Aq + 2048;
        const int bstep = NP * 32;

        // prefetch cursor at step s=2 (j=0, kt=2); Kt >= 8 always
        int pf_kt = 2, pf_j = 0;
        int pf_bi = (2 * NP + warpN) * 32 + lane;

        for (int j = 0; j < NPJ; ++j) {
            const int p0 = warpN + j * 8;
            float cq[2][2][2][4], ck[2][2][2][4];   // [np][mt][d2][4]
            #pragma unroll
            for (int a = 0; a < 2; a++)
                #pragma unroll
                for (int b = 0; b < 2; b++)
                    #pragma unroll
                    for (int d2 = 0; d2 < 2; d2++)
                        #pragma unroll
                        for (int i = 0; i < 4; i++) { cq[a][b][d2][i] = 0.f; ck[a][b][d2][i] = 0.f; }

            int bi = p0 * 32 + lane;

            #pragma unroll 1
            for (int kt = 0; kt < Kt; ++kt) {
                // prefetch step s+2 into L1 (4 lines worth of this lane's data)
                PF_L1(Bq + pf_bi);
                PF_L1(Bq + pf_bi + 128);
                PF_L1(Bk + pf_bi);
                PF_L1(Bk + pf_bi + 128);
                if (++pf_kt == Kt) {
                    pf_kt = 0;
                    pf_j = (pf_j + 1 < NPJ) ? pf_j + 1 : pf_j;   // clamp at last block
                    pf_bi = (warpN + pf_j * 8) * 32 + lane;
                } else {
                    pf_bi += bstep;
                }

                uint4 aq[2], ak[2];
                #pragma unroll
                for (int mt = 0; mt < 2; ++mt) {
                    int ai = ((2 * warpM + mt) * Kt + kt) * 32 + lane;
                    aq[mt] = Aq[ai]; ak[mt] = Ak[ai];
                }
                uint4 bq[2], bk[2];
                #pragma unroll
                for (int np = 0; np < 2; ++np) {
                    bq[np] = Bq[bi + np * 128];
                    bk[np] = Bk[bi + np * 128];
                }
                bi += bstep;

                #pragma unroll
                for (int np = 0; np < 2; ++np)
                    #pragma unroll
                    for (int mt = 0; mt < 2; ++mt) {
                        MMA(cq[np][mt][0], aq[mt], bq[np].x, bq[np].y);
                        MMA(cq[np][mt][1], aq[mt], bq[np].z, bq[np].w);
                        MMA(ck[np][mt][0], ak[mt], bk[np].x, bk[np].y);
                        MMA(ck[np][mt][1], ak[mt], bk[np].z, bk[np].w);
                    }
            }
            #pragma unroll
            for (int np = 0; np < 2; ++np)
                #pragma unroll
                for (int mt = 0; mt < 2; ++mt) {
                    pre[mt][0][np] += cq[np][mt][0][0] * ck[np][mt][0][0] + cq[np][mt][0][1] * ck[np][mt][0][1]
                                    + cq[np][mt][1][0] * ck[np][mt][1][0] + cq[np][mt][1][1] * ck[np][mt][1][1];
                    pre[mt][1][np] += cq[np][mt][0][2] * ck[np][mt][0][2] + cq[np][mt][0][3] * ck[np][mt][0][3]
                                    + cq[np][mt][1][2] * ck[np][mt][1][2] + cq[np][mt][1][3] * ck[np][mt][1][3];
                }
        }
    }

    // reduce over the 4-lane n-split group and store pre (unique writer per (e,h))
    #pragma unroll
    for (int a = 0; a < 2; a++)
        #pragma unroll
        for (int b = 0; b < 2; b++)
            #pragma unroll
            for (int c = 0; c < 2; c++) {
                float v = pre[a][b][c];
                v += __shfl_xor_sync(0xffffffffu, v, 1);
                v += __shfl_xor_sync(0xffffffffu, v, 2);
                pre[a][b][c] = v;
            }
    if ((lane & 3) == 0) {
        int gID = lane >> 2;
        #pragma unroll
        for (int mt = 0; mt < 2; ++mt)
            #pragma unroll
            for (int rh = 0; rh < 2; ++rh)
                #pragma unroll
                for (int np = 0; np < 2; ++np) {
                    int e = tileE + (2 * warpM + mt) * 16 + gID + rh * 8;
                    int h = warpN + np * 4;
                    if (e < E) g_pre[e * 8 + h] = 0.25f * pre[mt][rh][np];
                }
    }
}

// ---------------------------------------------------------------------------
// Segment softmax
// ---------------------------------------------------------------------------
__device__ __forceinline__ unsigned fenc(float f) {
    unsigned b = __float_as_uint(f);
    return (b & 0x80000000u) ? ~b : (b | 0x80000000u);
}
__device__ __forceinline__ float fdec(unsigned u) {
    unsigned b = (u & 0x80000000u) ? (u & 0x7FFFFFFFu) : ~u;
    return __uint_as_float(b);
}

__global__ void k_init() {
    int i = blockIdx.x * blockDim.x + threadIdx.x;
    if (i < NODECAP * 8) { g_segmax[i] = 0u; g_segsum[i] = 0.f; }
}
__global__ void k_max(int E, const int* __restrict__ index) {
    int i = blockIdx.x * blockDim.x + threadIdx.x;
    if (i >= E * 8) return;
    int e = i >> 3, h = i & 7;
    atomicMax(&g_segmax[index[e] * 8 + h], fenc(g_pre[i]));
}
__global__ void k_exp(int E, const int* __restrict__ index, float* __restrict__ out) {
    int i = blockIdx.x * blockDim.x + threadIdx.x;
    if (i >= E * 8) return;
    int e = i >> 3, h = i & 7;
    int seg = index[e] * 8 + h;
    float ex = expf(g_pre[i] - fdec(g_segmax[seg]));
    out[i] = ex;
    atomicAdd(&g_segsum[seg], ex);
}
__global__ void k_norm(int E, const int* __restrict__ index, float* __restrict__ out) {
    int i = blockIdx.x * blockDim.x + threadIdx.x;
    if (i >= E * 8) return;
    int e = i >> 3, h = i & 7;
    out[i] = out[i] / (g_segsum[index[e] * 8 + h] + 1e-16f);
}

// ---------------------------------------------------------------------------
extern "C" void kernel_launch(void* const* d_in, const int* in_sizes, int n_in,
                              void* d_out, int out_size) {
    const float* xq    = (const float*)d_in[0];
    const float* xk    = (const float*)d_in[1];
    const float* Wq    = (const float*)d_in[2];
    const float* Wk    = (const float*)d_in[3];
    const int*   index = (const int*)d_in[4];
    float* out = (float*)d_out;
    int E = in_sizes[0] / (9 * 64);

    cudaFuncSetAttribute(so2_attn_main, cudaFuncAttributeMaxDynamicSharedMemorySize, SMEM_BYTES);

    // our launch idx 3 == global idx 5 (2 hidden harness launches) for ncu -s 5 -c 1
    prep_w<<<(G_TOTAL + 255) / 256, 256>>>(Wq, 0);
    prep_w<<<(G_TOTAL + 255) / 256, 256>>>(Wk, 1);
    k_init<<<(NODECAP * 8 + 255) / 256, 256>>>();

    so2_attn_main<<<(E + 63) / 64, 256, SMEM_BYTES>>>(xq, xk, E);

    int nb = (E * 8 + 255) / 256;
    k_max <<<nb, 256>>>(E, index);
    k_exp <<<nb, 256>>>(E, index, out);
    k_norm<<<nb, 256>>>(E, index, out);
}

// round 11
// speedup vs baseline: 1.2938x; 1.2938x over previous
#include <cuda_runtime.h>
#include <cuda_fp16.h>
#include <math.h>
#include <stdint.h>

#define NODECAP 16384
#define G_TOTAL 237568   // 192*384 + 256*512 + 128*256
#define PRECAP  (1<<20)
#define SMEM_BYTES 98304    // 64KB A frags + 32KB per-warp B rings (8 x 2 x 2KB)

// Prepped fragment-major fp16 weights: [0]=q [1]=k
__device__ __align__(16) __half g_B[2][G_TOTAL];
__device__ float    g_pre[PRECAP];
__device__ unsigned g_segmax[NODECAP * 8];
__device__ float    g_segsum[NODECAP * 8];

__constant__ int c_ord[9] = {0, 2, 6, 3, 7, 1, 5, 8, 4};
__constant__ int c_KT[3]  = {12, 16, 8};
__constant__ int c_NP[3]  = {24, 32, 16};
__constant__ int c_NPJ[3] = {3, 4, 2};          // NP / 8
__constant__ int c_D[3]   = {192, 256, 128};
__constant__ int c_IB0[3] = {0, 3, 7};
__constant__ int c_B4[3]  = {0, 9216, 25600};   // uint4 base per group

// ---------------------------------------------------------------------------
// Weight prep: dense W_eff per |m| group (sign pattern folded), fp16,
// exact mma.m16n8k16 B-fragment order, n8 pairs packed 8 halfs/lane.
// ---------------------------------------------------------------------------
__global__ void prep_w(const float* __restrict__ W, int mat) {
    int idx = blockIdx.x * blockDim.x + threadIdx.x;
    if (idx >= G_TOTAL) return;
    int g, kk, n, NP, boff, rem = idx;
    if (rem < 73728)       { g = 0; kk = rem / 384; n = rem % 384; NP = 24; boff = 0; }
    else if (rem < 204800) { rem -= 73728;  g = 1; kk = rem / 512; n = rem % 512; NP = 32; boff = 73728; }
    else                   { rem -= 204800; g = 2; kk = rem / 256; n = rem % 256; NP = 16; boff = 204800; }

    int c = kk & 63, d = n & 127, ib = kk >> 6, ob = n >> 7;
    int w; float s = 1.0f;
    if (g == 0) {
        w = ib * 3 + ob;
    } else if (g == 1) {
        int i = ib & 1, o = ob & 1;
        bool ip = ib < 2, op = ob < 2;
        int base = 9 + i * 4 + o * 2;
        if (ip && op)        w = base;                   // +Wr
        else if (!ip && op)  { w = base + 1; s = -1.f; } // -Wi
        else if (ip && !op)  w = base + 1;               // +Wi
        else                 w = base;                   // +Wr
    } else {
        bool ip = (ib == 0), op = (ob == 0);
        if (ip && op)        w = 17;
        else if (!ip && op)  { w = 18; s = -1.f; }
        else if (ip && !op)  w = 18;
        else                 w = 17;
    }
    int widx = (w * 64 + c) * 128 + d;

    int kt = kk >> 4, k16 = kk & 15, n8 = n >> 3;
    int lane = (n & 7) * 4 + ((k16 & 7) >> 1);
    int slot = (k16 & 1) + ((k16 >> 3) << 1);
    int off  = boff + ((kt * NP + (n8 >> 1)) * 32 + lane) * 8 + ((n8 & 1) << 2) + slot;

    g_B[mat][off] = __float2half(s * W[widx]);
}

// ---------------------------------------------------------------------------
__device__ __forceinline__ uint32_t s2u(const void* p) {
    uint32_t a;
    asm("{ .reg .u64 t; cvta.to.shared.u64 t, %1; cvt.u32.u64 %0, t; }" : "=r"(a) : "l"(p));
    return a;
}
#define CPA16(d, sp)  asm volatile("cp.async.cg.shared.global [%0], [%1], 16;" :: "r"(d), "l"(sp) : "memory")
#define CPA_COMMIT()  asm volatile("cp.async.commit_group;" ::: "memory")
#define CPA_WAIT0()   asm volatile("cp.async.wait_group 0;" ::: "memory")
#define CPA_WAIT1()   asm volatile("cp.async.wait_group 1;" ::: "memory")

#define MMA(c, a, b0, b1) asm volatile( \
    "mma.sync.aligned.m16n8k16.row.col.f32.f16.f16.f32 " \
    "{%0,%1,%2,%3},{%4,%5,%6,%7},{%8,%9},{%0,%1,%2,%3};\n" \
    : "+f"((c)[0]), "+f"((c)[1]), "+f"((c)[2]), "+f"((c)[3]) \
    : "r"((a).x), "r"((a).y), "r"((a).z), "r"((a).w), "r"(b0), "r"(b1))

__global__ __launch_bounds__(256, 2)
void so2_attn_main(const float* __restrict__ xq, const float* __restrict__ xk, int E) {
    extern __shared__ __half sA[];   // [0]=q frags (16384 halfs), [16384]=k frags
    uint4* sB = (uint4*)(sA + 32768);        // per-warp rings: warp*256 + stage*128 uint4
    const int tid = threadIdx.x, lane = tid & 31, warp = tid >> 5;
    const int warpM = warp & 1, warpN = warp >> 1;
    const int tileE = blockIdx.x * 64;
    const uint32_t wring_u32 = s2u(sB) + ((warp * 256 + lane) << 4);

    float pre[2][2][2];   // [mt][rowhalf][np] ; head = warpN + np*4
    #pragma unroll
    for (int a = 0; a < 2; a++)
        #pragma unroll
        for (int b = 0; b < 2; b++)
            #pragma unroll
            for (int c = 0; c < 2; c++) pre[a][b][c] = 0.f;

    for (int g = 0; g < 3; ++g) {
        const int Kt = c_KT[g], NP = c_NP[g], NPJ = c_NPJ[g], D = c_D[g];
        __syncthreads();   // previous group's compute fully done before rewriting sA
        // ---- convert x slice -> fragment-major fp16 smem (64 edges) ----
        const int nq = 64 * (D >> 2);
        #pragma unroll
        for (int t = 0; t < 2; ++t) {
            const float* x = t ? xk : xq;
            __half* A = sA + t * 16384;
            for (int q0 = tid; q0 < nq; q0 += 256) {
                int el = q0 / (D >> 2), c = (q0 % (D >> 2)) * 4;
                int ord = c_ord[c_IB0[g] + (c >> 6)];
                int e = tileE + el;
                float4 v = make_float4(0.f, 0.f, 0.f, 0.f);
                if (e < E) v = *(const float4*)(x + ((size_t)e * 9 + ord) * 64 + (c & 63));
                int r = el & 15, mtile = el >> 4;
                int kt = c >> 4, kk0 = c & 15;
                int ln0 = (r & 7) * 4 + ((kk0 & 7) >> 1);
                int hx  = (((kk0 >> 3) << 1) + (r >> 3)) * 2;
                int off = ((mtile * Kt + kt) * 32 + ln0) * 8 + hx;
                *(__half2*)(A + off)     = __floats2half2_rn(v.x, v.y);
                *(__half2*)(A + off + 8) = __floats2half2_rn(v.z, v.w);
            }
        }
        __syncthreads();

        // ---- fused fp16 GEMMs + per-head q*k reduction ----
        // Per-warp private 2-stage cp.async ring for B: no CTA barriers in
        // the mainloop; each warp paces itself (wait_group + syncwarp only).
        const uint4* Bq = (const uint4*)g_B[0] + c_B4[g];
        const uint4* Bk = (const uint4*)g_B[1] + c_B4[g];
        const uint4* Aq = (const uint4*)sA;
        const uint4* Ak = Aq + 2048;
        const uint4* wring = sB + warp * 256;
        const int bstep = NP * 32;
        const int S = NPJ * Kt;

        // ISSUE one step's B (2 q-pairs + 2 k-pairs) into stage slot
        #define ISSUE_W(bi_, slot_) do { \
            uint32_t _d = wring_u32 + ((slot_) << 11); \
            CPA16(_d,        Bq + (bi_)); \
            CPA16(_d + 512,  Bq + (bi_) + 128); \
            CPA16(_d + 1024, Bk + (bi_)); \
            CPA16(_d + 1536, Bk + (bi_) + 128); \
            CPA_COMMIT(); \
        } while (0)

        // prologue: issue steps 0,1 ; cursor at step 2
        ISSUE_W(warpN * 32 + lane, 0);
        ISSUE_W((NP + warpN) * 32 + lane, 1);
        int pf_kt = 2, pf_j = 0;
        int pf_bi = (2 * NP + warpN) * 32 + lane;

        int s = 0;
        for (int j = 0; j < NPJ; ++j) {
            float cq[2][2][2][4], ck[2][2][2][4];   // [np][mt][d2][4]
            #pragma unroll
            for (int a = 0; a < 2; a++)
                #pragma unroll
                for (int b = 0; b < 2; b++)
                    #pragma unroll
                    for (int d2 = 0; d2 < 2; d2++)
                        #pragma unroll
                        for (int i = 0; i < 4; i++) { cq[a][b][d2][i] = 0.f; ck[a][b][d2][i] = 0.f; }

            #pragma unroll 1
            for (int kt = 0; kt < Kt; ++kt, ++s) {
                if (s + 1 < S) CPA_WAIT1(); else CPA_WAIT0();
                __syncwarp();

                const uint4* slotp = wring + ((s & 1) << 7);
                uint4 bq[2], bk[2];
                bq[0] = slotp[lane];      bq[1] = slotp[32 + lane];
                bk[0] = slotp[64 + lane]; bk[1] = slotp[96 + lane];

                uint4 aq[2], ak[2];
                #pragma unroll
                for (int mt = 0; mt < 2; ++mt) {
                    int ai = ((2 * warpM + mt) * Kt + kt) * 32 + lane;
                    aq[mt] = Aq[ai]; ak[mt] = Ak[ai];
                }

                #pragma unroll
                for (int np = 0; np < 2; ++np)
                    #pragma unroll
                    for (int mt = 0; mt < 2; ++mt) {
                        MMA(cq[np][mt][0], aq[mt], bq[np].x, bq[np].y);
                        MMA(cq[np][mt][1], aq[mt], bq[np].z, bq[np].w);
                        MMA(ck[np][mt][0], ak[mt], bk[np].x, bk[np].y);
                        MMA(ck[np][mt][1], ak[mt], bk[np].z, bk[np].w);
                    }

                // refill this slot with step s+2 (all lanes' LDS above have
                // completed: their results feed the MMAs already issued)
                if (s + 2 < S) {
                    ISSUE_W(pf_bi, s & 1);
                    if (++pf_kt == Kt) {
                        pf_kt = 0; ++pf_j;
                        pf_bi = (warpN + pf_j * 8) * 32 + lane;
                    } else {
                        pf_bi += bstep;
                    }
                }
            }
            #pragma unroll
            for (int np = 0; np < 2; ++np)
                #pragma unroll
                for (int mt = 0; mt < 2; ++mt) {
                    pre[mt][0][np] += cq[np][mt][0][0] * ck[np][mt][0][0] + cq[np][mt][0][1] * ck[np][mt][0][1]
                                    + cq[np][mt][1][0] * ck[np][mt][1][0] + cq[np][mt][1][1] * ck[np][mt][1][1];
                    pre[mt][1][np] += cq[np][mt][0][2] * ck[np][mt][0][2] + cq[np][mt][0][3] * ck[np][mt][0][3]
                                    + cq[np][mt][1][2] * ck[np][mt][1][2] + cq[np][mt][1][3] * ck[np][mt][1][3];
                }
        }
        #undef ISSUE_W
    }

    // reduce over the 4-lane n-split group and store pre (unique writer per (e,h))
    #pragma unroll
    for (int a = 0; a < 2; a++)
        #pragma unroll
        for (int b = 0; b < 2; b++)
            #pragma unroll
            for (int c = 0; c < 2; c++) {
                float v = pre[a][b][c];
                v += __shfl_xor_sync(0xffffffffu, v, 1);
                v += __shfl_xor_sync(0xffffffffu, v, 2);
                pre[a][b][c] = v;
            }
    if ((lane & 3) == 0) {
        int gID = lane >> 2;
        #pragma unroll
        for (int mt = 0; mt < 2; ++mt)
            #pragma unroll
            for (int rh = 0; rh < 2; ++rh)
                #pragma unroll
                for (int np = 0; np < 2; ++np) {
                    int e = tileE + (2 * warpM + mt) * 16 + gID + rh * 8;
                    int h = warpN + np * 4;
                    if (e < E) g_pre[e * 8 + h] = 0.25f * pre[mt][rh][np];
                }
    }
}

// ---------------------------------------------------------------------------
// Segment softmax
// ---------------------------------------------------------------------------
__device__ __forceinline__ unsigned fenc(float f) {
    unsigned b = __float_as_uint(f);
    return (b & 0x80000000u) ? ~b : (b | 0x80000000u);
}
__device__ __forceinline__ float fdec(unsigned u) {
    unsigned b = (u & 0x80000000u) ? (u & 0x7FFFFFFFu) : ~u;
    return __uint_as_float(b);
}

__global__ void k_init() {
    int i = blockIdx.x * blockDim.x + threadIdx.x;
    if (i < NODECAP * 8) { g_segmax[i] = 0u; g_segsum[i] = 0.f; }
}
__global__ void k_max(int E, const int* __restrict__ index) {
    int i = blockIdx.x * blockDim.x + threadIdx.x;
    if (i >= E * 8) return;
    int e = i >> 3, h = i & 7;
    atomicMax(&g_segmax[index[e] * 8 + h], fenc(g_pre[i]));
}
__global__ void k_exp(int E, const int* __restrict__ index, float* __restrict__ out) {
    int i = blockIdx.x * blockDim.x + threadIdx.x;
    if (i >= E * 8) return;
    int e = i >> 3, h = i & 7;
    int seg = index[e] * 8 + h;
    float ex = expf(g_pre[i] - fdec(g_segmax[seg]));
    out[i] = ex;
    atomicAdd(&g_segsum[seg], ex);
}
__global__ void k_norm(int E, const int* __restrict__ index, float* __restrict__ out) {
    int i = blockIdx.x * blockDim.x + threadIdx.x;
    if (i >= E * 8) return;
    int e = i >> 3, h = i & 7;
    out[i] = out[i] / (g_segsum[index[e] * 8 + h] + 1e-16f);
}

// ---------------------------------------------------------------------------
extern "C" void kernel_launch(void* const* d_in, const int* in_sizes, int n_in,
                              void* d_out, int out_size) {
    const float* xq    = (const float*)d_in[0];
    const float* xk    = (const float*)d_in[1];
    const float* Wq    = (const float*)d_in[2];
    const float* Wk    = (const float*)d_in[3];
    const int*   index = (const int*)d_in[4];
    float* out = (float*)d_out;
    int E = in_sizes[0] / (9 * 64);

    cudaFuncSetAttribute(so2_attn_main, cudaFuncAttributeMaxDynamicSharedMemorySize, SMEM_BYTES);

    // our launch idx 3 == global idx 5 (2 hidden harness launches) for ncu -s 5 -c 1
    prep_w<<<(G_TOTAL + 255) / 256, 256>>>(Wq, 0);
    prep_w<<<(G_TOTAL + 255) / 256, 256>>>(Wk, 1);
    k_init<<<(NODECAP * 8 + 255) / 256, 256>>>();

    so2_attn_main<<<(E + 63) / 64, 256, SMEM_BYTES>>>(xq, xk, E);

    int nb = (E * 8 + 255) / 256;
    k_max <<<nb, 256>>>(E, index);
    k_exp <<<nb, 256>>>(E, index, out);
    k_norm<<<nb, 256>>>(E, index, out);
}

// round 12
// speedup vs baseline: 1.3862x; 1.0715x over previous
#include <cuda_runtime.h>
#include <cuda_fp16.h>
#include <math.h>
#include <stdint.h>

#define NODECAP 16384
#define G_TOTAL 237568   // 192*384 + 256*512 + 128*256
#define PRECAP  (1<<20)
#define SMEM_BYTES 114688   // 64KB A frags + 48KB per-warp B rings (8 x 3 x 2KB)

// Prepped fragment-major fp16 weights: [0]=q [1]=k
__device__ __align__(16) __half g_B[2][G_TOTAL];
__device__ float    g_pre[PRECAP];
__device__ unsigned g_segmax[NODECAP * 8];
__device__ float    g_segsum[NODECAP * 8];

__constant__ int c_ord[9] = {0, 2, 6, 3, 7, 1, 5, 8, 4};
__constant__ int c_KT[3]  = {12, 16, 8};
__constant__ int c_NP[3]  = {24, 32, 16};
__constant__ int c_NPJ[3] = {3, 4, 2};          // NP / 8
__constant__ int c_D[3]   = {192, 256, 128};
__constant__ int c_IB0[3] = {0, 3, 7};
__constant__ int c_B4[3]  = {0, 9216, 25600};   // uint4 base per group

// ---------------------------------------------------------------------------
// Weight prep: dense W_eff per |m| group (sign pattern folded), fp16,
// exact mma.m16n8k16 B-fragment order, n8 pairs packed 8 halfs/lane.
// ---------------------------------------------------------------------------
__global__ void prep_w(const float* __restrict__ W, int mat) {
    int idx = blockIdx.x * blockDim.x + threadIdx.x;
    if (idx >= G_TOTAL) return;
    int g, kk, n, NP, boff, rem = idx;
    if (rem < 73728)       { g = 0; kk = rem / 384; n = rem % 384; NP = 24; boff = 0; }
    else if (rem < 204800) { rem -= 73728;  g = 1; kk = rem / 512; n = rem % 512; NP = 32; boff = 73728; }
    else                   { rem -= 204800; g = 2; kk = rem / 256; n = rem % 256; NP = 16; boff = 204800; }

    int c = kk & 63, d = n & 127, ib = kk >> 6, ob = n >> 7;
    int w; float s = 1.0f;
    if (g == 0) {
        w = ib * 3 + ob;
    } else if (g == 1) {
        int i = ib & 1, o = ob & 1;
        bool ip = ib < 2, op = ob < 2;
        int base = 9 + i * 4 + o * 2;
        if (ip && op)        w = base;                   // +Wr
        else if (!ip && op)  { w = base + 1; s = -1.f; } // -Wi
        else if (ip && !op)  w = base + 1;               // +Wi
        else                 w = base;                   // +Wr
    } else {
        bool ip = (ib == 0), op = (ob == 0);
        if (ip && op)        w = 17;
        else if (!ip && op)  { w = 18; s = -1.f; }
        else if (ip && !op)  w = 18;
        else                 w = 17;
    }
    int widx = (w * 64 + c) * 128 + d;

    int kt = kk >> 4, k16 = kk & 15, n8 = n >> 3;
    int lane = (n & 7) * 4 + ((k16 & 7) >> 1);
    int slot = (k16 & 1) + ((k16 >> 3) << 1);
    int off  = boff + ((kt * NP + (n8 >> 1)) * 32 + lane) * 8 + ((n8 & 1) << 2) + slot;

    g_B[mat][off] = __float2half(s * W[widx]);
}

// ---------------------------------------------------------------------------
__device__ __forceinline__ uint32_t s2u(const void* p) {
    uint32_t a;
    asm("{ .reg .u64 t; cvta.to.shared.u64 t, %1; cvt.u32.u64 %0, t; }" : "=r"(a) : "l"(p));
    return a;
}
#define CPA16(d, sp)  asm volatile("cp.async.cg.shared.global [%0], [%1], 16;" :: "r"(d), "l"(sp) : "memory")
#define CPA_COMMIT()  asm volatile("cp.async.commit_group;" ::: "memory")
#define CPA_WAIT0()   asm volatile("cp.async.wait_group 0;" ::: "memory")
#define CPA_WAIT1()   asm volatile("cp.async.wait_group 1;" ::: "memory")
#define CPA_WAIT2()   asm volatile("cp.async.wait_group 2;" ::: "memory")

#define MMA(c, a, b0, b1) asm volatile( \
    "mma.sync.aligned.m16n8k16.row.col.f32.f16.f16.f32 " \
    "{%0,%1,%2,%3},{%4,%5,%6,%7},{%8,%9},{%0,%1,%2,%3};\n" \
    : "+f"((c)[0]), "+f"((c)[1]), "+f"((c)[2]), "+f"((c)[3]) \
    : "r"((a).x), "r"((a).y), "r"((a).z), "r"((a).w), "r"(b0), "r"(b1))

__global__ __launch_bounds__(256, 2)
void so2_attn_main(const float* __restrict__ xq, const float* __restrict__ xk, int E) {
    extern __shared__ __half sA[];   // [0]=q frags (16384 halfs), [16384]=k frags
    uint4* sB = (uint4*)(sA + 32768);        // per-warp rings: warp*384 + slot*128 uint4
    const int tid = threadIdx.x, lane = tid & 31, warp = tid >> 5;
    const int warpM = warp & 1, warpN = warp >> 1;
    const int tileE = blockIdx.x * 64;
    const uint32_t wring_u32 = s2u(sB) + ((warp * 384 + lane) << 4);
    const uint4* wring = sB + warp * 384;

    float pre[2][2][2];   // [mt][rowhalf][np] ; head = warpN + np*4
    #pragma unroll
    for (int a = 0; a < 2; a++)
        #pragma unroll
        for (int b = 0; b < 2; b++)
            #pragma unroll
            for (int c = 0; c < 2; c++) pre[a][b][c] = 0.f;

    for (int g = 0; g < 3; ++g) {
        const int Kt = c_KT[g], NP = c_NP[g], NPJ = c_NPJ[g], D = c_D[g];
        __syncthreads();   // previous group's compute fully done before rewriting sA
        // ---- convert x slice -> fragment-major fp16 smem (64 edges) ----
        const int nq = 64 * (D >> 2);
        #pragma unroll
        for (int t = 0; t < 2; ++t) {
            const float* x = t ? xk : xq;
            __half* A = sA + t * 16384;
            for (int q0 = tid; q0 < nq; q0 += 256) {
                int el = q0 / (D >> 2), c = (q0 % (D >> 2)) * 4;
                int ord = c_ord[c_IB0[g] + (c >> 6)];
                int e = tileE + el;
                float4 v = make_float4(0.f, 0.f, 0.f, 0.f);
                if (e < E) v = *(const float4*)(x + ((size_t)e * 9 + ord) * 64 + (c & 63));
                int r = el & 15, mtile = el >> 4;
                int kt = c >> 4, kk0 = c & 15;
                int ln0 = (r & 7) * 4 + ((kk0 & 7) >> 1);
                int hx  = (((kk0 >> 3) << 1) + (r >> 3)) * 2;
                int off = ((mtile * Kt + kt) * 32 + ln0) * 8 + hx;
                *(__half2*)(A + off)     = __floats2half2_rn(v.x, v.y);
                *(__half2*)(A + off + 8) = __floats2half2_rn(v.z, v.w);
            }
        }
        __syncthreads();

        // ---- fused fp16 GEMMs + per-head q*k reduction ----
        // Per-warp private 3-stage cp.async ring for B, distance ~3 steps.
        // No barriers, no syncwarp: every lane reads exactly the slots its
        // own cp.async wrote, and wait_group is per-thread.
        const uint4* Bq = (const uint4*)g_B[0] + c_B4[g];
        const uint4* Bk = (const uint4*)g_B[1] + c_B4[g];
        const uint4* Aq = (const uint4*)sA;
        const uint4* Ak = Aq + 2048;
        const int bstep = NP * 32;
        const int S = NPJ * Kt;

        #define ISSUE_W(bi_, slot_) do { \
            uint32_t _d = wring_u32 + (uint32_t)((slot_) << 11); \
            CPA16(_d,        Bq + (bi_)); \
            CPA16(_d + 512,  Bq + (bi_) + 128); \
            CPA16(_d + 1024, Bk + (bi_)); \
            CPA16(_d + 1536, Bk + (bi_) + 128); \
            CPA_COMMIT(); \
        } while (0)

        // prologue: fill steps 0,1,2 (all j=0; Kt >= 8); cursor at step 3
        ISSUE_W(warpN * 32 + lane, 0);
        ISSUE_W((NP + warpN) * 32 + lane, 1);
        ISSUE_W((2 * NP + warpN) * 32 + lane, 2);
        int pf_kt = 3, pf_j = 0;
        int pf_bi = (3 * NP + warpN) * 32 + lane;

        int s = 0, slot = 0;
        for (int j = 0; j < NPJ; ++j) {
            float cq[2][2][2][4], ck[2][2][2][4];   // [np][mt][d2][4]
            #pragma unroll
            for (int a = 0; a < 2; a++)
                #pragma unroll
                for (int b = 0; b < 2; b++)
                    #pragma unroll
                    for (int d2 = 0; d2 < 2; d2++)
                        #pragma unroll
                        for (int i = 0; i < 4; i++) { cq[a][b][d2][i] = 0.f; ck[a][b][d2][i] = 0.f; }

            #pragma unroll 1
            for (int kt = 0; kt < Kt; ++kt, ++s) {
                if (s + 3 <= S - 1 + 1 - 1) { /* s <= S-3 */ }
                if (s <= S - 3) CPA_WAIT2();
                else if (s == S - 2) CPA_WAIT1();
                else CPA_WAIT0();

                const uint4* slotp = wring + (slot << 7);
                uint4 bq[2], bk[2];
                bq[0] = slotp[lane];      bq[1] = slotp[32 + lane];
                bk[0] = slotp[64 + lane]; bk[1] = slotp[96 + lane];

                // refill this slot with step s+3 right away (per-thread
                // program order: our LDS above precede the async writes)
                if (s + 3 < S) {
                    ISSUE_W(pf_bi, slot);
                    if (++pf_kt == Kt) {
                        pf_kt = 0; ++pf_j;
                        pf_bi = (warpN + pf_j * 8) * 32 + lane;
                    } else {
                        pf_bi += bstep;
                    }
                }

                uint4 aq[2], ak[2];
                #pragma unroll
                for (int mt = 0; mt < 2; ++mt) {
                    int ai = ((2 * warpM + mt) * Kt + kt) * 32 + lane;
                    aq[mt] = Aq[ai]; ak[mt] = Ak[ai];
                }

                #pragma unroll
                for (int np = 0; np < 2; ++np)
                    #pragma unroll
                    for (int mt = 0; mt < 2; ++mt) {
                        MMA(cq[np][mt][0], aq[mt], bq[np].x, bq[np].y);
                        MMA(cq[np][mt][1], aq[mt], bq[np].z, bq[np].w);
                        MMA(ck[np][mt][0], ak[mt], bk[np].x, bk[np].y);
                        MMA(ck[np][mt][1], ak[mt], bk[np].z, bk[np].w);
                    }

                if (++slot == 3) slot = 0;
            }
            #pragma unroll
            for (int np = 0; np < 2; ++np)
                #pragma unroll
                for (int mt = 0; mt < 2; ++mt) {
                    pre[mt][0][np] += cq[np][mt][0][0] * ck[np][mt][0][0] + cq[np][mt][0][1] * ck[np][mt][0][1]
                                    + cq[np][mt][1][0] * ck[np][mt][1][0] + cq[np][mt][1][1] * ck[np][mt][1][1];
                    pre[mt][1][np] += cq[np][mt][0][2] * ck[np][mt][0][2] + cq[np][mt][0][3] * ck[np][mt][0][3]
                                    + cq[np][mt][1][2] * ck[np][mt][1][2] + cq[np][mt][1][3] * ck[np][mt][1][3];
                }
        }
        #undef ISSUE_W
    }

    // reduce over the 4-lane n-split group and store pre (unique writer per (e,h))
    #pragma unroll
    for (int a = 0; a < 2; a++)
        #pragma unroll
        for (int b = 0; b < 2; b++)
            #pragma unroll
            for (int c = 0; c < 2; c++) {
                float v = pre[a][b][c];
                v += __shfl_xor_sync(0xffffffffu, v, 1);
                v += __shfl_xor_sync(0xffffffffu, v, 2);
                pre[a][b][c] = v;
            }
    if ((lane & 3) == 0) {
        int gID = lane >> 2;
        #pragma unroll
        for (int mt = 0; mt < 2; ++mt)
            #pragma unroll
            for (int rh = 0; rh < 2; ++rh)
                #pragma unroll
                for (int np = 0; np < 2; ++np) {
                    int e = tileE + (2 * warpM + mt) * 16 + gID + rh * 8;
                    int h = warpN + np * 4;
                    if (e < E) g_pre[e * 8 + h] = 0.25f * pre[mt][rh][np];
                }
    }
}

// ---------------------------------------------------------------------------
// Segment softmax
// ---------------------------------------------------------------------------
__device__ __forceinline__ unsigned fenc(float f) {
    unsigned b = __float_as_uint(f);
    return (b & 0x80000000u) ? ~b : (b | 0x80000000u);
}
__device__ __forceinline__ float fdec(unsigned u) {
    unsigned b = (u & 0x80000000u) ? (u & 0x7FFFFFFFu) : ~u;
    return __uint_as_float(b);
}

__global__ void k_init() {
    int i = blockIdx.x * blockDim.x + threadIdx.x;
    if (i < NODECAP * 8) { g_segmax[i] = 0u; g_segsum[i] = 0.f; }
}
__global__ void k_max(int E, const int* __restrict__ index) {
    int i = blockIdx.x * blockDim.x + threadIdx.x;
    if (i >= E * 8) return;
    int e = i >> 3, h = i & 7;
    atomicMax(&g_segmax[index[e] * 8 + h], fenc(g_pre[i]));
}
__global__ void k_exp(int E, const int* __restrict__ index, float* __restrict__ out) {
    int i = blockIdx.x * blockDim.x + threadIdx.x;
    if (i >= E * 8) return;
    int e = i >> 3, h = i & 7;
    int seg = index[e] * 8 + h;
    float ex = expf(g_pre[i] - fdec(g_segmax[seg]));
    out[i] = ex;
    atomicAdd(&g_segsum[seg], ex);
}
__global__ void k_norm(int E, const int* __restrict__ index, float* __restrict__ out) {
    int i = blockIdx.x * blockDim.x + threadIdx.x;
    if (i >= E * 8) return;
    int e = i >> 3, h = i & 7;
    out[i] = out[i] / (g_segsum[index[e] * 8 + h] + 1e-16f);
}

// ---------------------------------------------------------------------------
extern "C" void kernel_launch(void* const* d_in, const int* in_sizes, int n_in,
                              void* d_out, int out_size) {
    const float* xq    = (const float*)d_in[0];
    const float* xk    = (const float*)d_in[1];
    const float* Wq    = (const float*)d_in[2];
    const float* Wk    = (const float*)d_in[3];
    const int*   index = (const int*)d_in[4];
    float* out = (float*)d_out;
    int E = in_sizes[0] / (9 * 64);

    cudaFuncSetAttribute(so2_attn_main, cudaFuncAttributeMaxDynamicSharedMemorySize, SMEM_BYTES);

    // our launch idx 3 == global idx 5 (2 hidden harness launches) for ncu -s 5 -c 1
    prep_w<<<(G_TOTAL + 255) / 256, 256>>>(Wq, 0);
    prep_w<<<(G_TOTAL + 255) / 256, 256>>>(Wk, 1);
    k_init<<<(NODECAP * 8 + 255) / 256, 256>>>();

    so2_attn_main<<<(E + 63) / 64, 256, SMEM_BYTES>>>(xq, xk, E);

    int nb = (E * 8 + 255) / 256;
    k_max <<<nb, 256>>>(E, index);
    k_exp <<<nb, 256>>>(E, index, out);
    k_norm<<<nb, 256>>>(E, index, out);
}